// round 4
// baseline (speedup 1.0000x reference)
#include <cuda_runtime.h>

#define BN 4096
#define DN 768
#define PN 96
#define CN 256
#define SDN 8

typedef unsigned long long u64;

__device__ __forceinline__ u64 ffma2(u64 a, u64 b, u64 c) {
    u64 d;
    asm("fma.rn.f32x2 %0, %1, %2, %3;" : "=l"(d) : "l"(a), "l"(b), "l"(c));
    return d;
}
__device__ __forceinline__ u64 fmul2(u64 a, u64 b) {
    u64 d;
    asm("mul.rn.f32x2 %0, %1, %2;" : "=l"(d) : "l"(a), "l"(b));
    return d;
}
__device__ __forceinline__ u64 pack2(float lo, float hi) {
    u64 r;
    asm("mov.b64 %0, {%1, %2};" : "=l"(r) : "f"(lo), "f"(hi));
    return r;
}
__device__ __forceinline__ void unpack2(u64 v, float& lo, float& hi) {
    asm("mov.b64 {%0, %1}, %2;" : "=f"(lo), "=f"(hi) : "l"(v));
}

// Block: 128 threads, covers 256 batch vectors (2 per thread) for one partition p.
// Grid: (BN/256 = 16, PN = 96).
__global__ __launch_bounds__(128) void pq_argmax_kernel(
    const float* __restrict__ vecs,
    const float* __restrict__ codebook,
    float* __restrict__ out)
{
    // Pair-interleaved codebook: row j (16 floats) = {c0_d0,c1_d0,c0_d1,c1_d1,...}
    // where c0 = 2j, c1 = 2j+1. One LDS.128 yields two packed f32x2 operands.
    __shared__ __align__(16) float cbi[CN * SDN];
    __shared__ __align__(8)  float csq[CN];   // +||c||^2, natural c order

    const int t = threadIdx.x;
    const int p = blockIdx.y;
    const float* cb = codebook + (size_t)p * CN * SDN;

    // ---- init: thread t stages centroid pair (2t, 2t+1) ----
    {
        const float4* cb4 = (const float4*)cb + t * 4;
        float4 c0lo = cb4[0], c0hi = cb4[1];   // centroid 2t,   dims 0-3 / 4-7
        float4 c1lo = cb4[2], c1hi = cb4[3];   // centroid 2t+1

        // c_sq: elementwise square (rn) then sequential add (rn), no fma —
        // reproduces jnp.sum(codebook*codebook, axis=-1) rounding.
        float q0 = __fmul_rn(c0lo.x, c0lo.x);
        q0 = __fadd_rn(q0, __fmul_rn(c0lo.y, c0lo.y));
        q0 = __fadd_rn(q0, __fmul_rn(c0lo.z, c0lo.z));
        q0 = __fadd_rn(q0, __fmul_rn(c0lo.w, c0lo.w));
        q0 = __fadd_rn(q0, __fmul_rn(c0hi.x, c0hi.x));
        q0 = __fadd_rn(q0, __fmul_rn(c0hi.y, c0hi.y));
        q0 = __fadd_rn(q0, __fmul_rn(c0hi.z, c0hi.z));
        q0 = __fadd_rn(q0, __fmul_rn(c0hi.w, c0hi.w));
        float q1 = __fmul_rn(c1lo.x, c1lo.x);
        q1 = __fadd_rn(q1, __fmul_rn(c1lo.y, c1lo.y));
        q1 = __fadd_rn(q1, __fmul_rn(c1lo.z, c1lo.z));
        q1 = __fadd_rn(q1, __fmul_rn(c1lo.w, c1lo.w));
        q1 = __fadd_rn(q1, __fmul_rn(c1hi.x, c1hi.x));
        q1 = __fadd_rn(q1, __fmul_rn(c1hi.y, c1hi.y));
        q1 = __fadd_rn(q1, __fmul_rn(c1hi.z, c1hi.z));
        q1 = __fadd_rn(q1, __fmul_rn(c1hi.w, c1hi.w));

        float4* row = (float4*)(cbi + t * 16);
        row[0] = make_float4(c0lo.x, c1lo.x, c0lo.y, c1lo.y);
        row[1] = make_float4(c0lo.z, c1lo.z, c0lo.w, c1lo.w);
        row[2] = make_float4(c0hi.x, c1hi.x, c0hi.y, c1hi.y);
        row[3] = make_float4(c0hi.z, c1hi.z, c0hi.w, c1hi.w);
        csq[2 * t]     = q0;
        csq[2 * t + 1] = q1;
    }

    // ---- load the two sub-vectors this thread owns ----
    const int b0 = blockIdx.x * 256 + t;
    const int b1 = b0 + 128;
    const float4* va4 = (const float4*)(vecs + (size_t)b0 * DN + p * SDN);
    const float4* vb4 = (const float4*)(vecs + (size_t)b1 * DN + p * SDN);
    float4 va0 = va4[0], va1 = va4[1];
    float4 vb0 = vb4[0], vb1 = vb4[1];

    // v_sq: same elementwise-square + sequential-add rounding as reference.
    float vsA = __fmul_rn(va0.x, va0.x);
    vsA = __fadd_rn(vsA, __fmul_rn(va0.y, va0.y));
    vsA = __fadd_rn(vsA, __fmul_rn(va0.z, va0.z));
    vsA = __fadd_rn(vsA, __fmul_rn(va0.w, va0.w));
    vsA = __fadd_rn(vsA, __fmul_rn(va1.x, va1.x));
    vsA = __fadd_rn(vsA, __fmul_rn(va1.y, va1.y));
    vsA = __fadd_rn(vsA, __fmul_rn(va1.z, va1.z));
    vsA = __fadd_rn(vsA, __fmul_rn(va1.w, va1.w));
    float vsB = __fmul_rn(vb0.x, vb0.x);
    vsB = __fadd_rn(vsB, __fmul_rn(vb0.y, vb0.y));
    vsB = __fadd_rn(vsB, __fmul_rn(vb0.z, vb0.z));
    vsB = __fadd_rn(vsB, __fmul_rn(vb0.w, vb0.w));
    vsB = __fadd_rn(vsB, __fmul_rn(vb1.x, vb1.x));
    vsB = __fadd_rn(vsB, __fmul_rn(vb1.y, vb1.y));
    vsB = __fadd_rn(vsB, __fmul_rn(vb1.z, vb1.z));
    vsB = __fadd_rn(vsB, __fmul_rn(vb1.w, vb1.w));

    u64 wa[8], wb[8];
    wa[0] = pack2(va0.x, va0.x); wa[1] = pack2(va0.y, va0.y);
    wa[2] = pack2(va0.z, va0.z); wa[3] = pack2(va0.w, va0.w);
    wa[4] = pack2(va1.x, va1.x); wa[5] = pack2(va1.y, va1.y);
    wa[6] = pack2(va1.z, va1.z); wa[7] = pack2(va1.w, va1.w);
    wb[0] = pack2(vb0.x, vb0.x); wb[1] = pack2(vb0.y, vb0.y);
    wb[2] = pack2(vb0.z, vb0.z); wb[3] = pack2(vb0.w, vb0.w);
    wb[4] = pack2(vb1.x, vb1.x); wb[5] = pack2(vb1.y, vb1.y);
    wb[6] = pack2(vb1.z, vb1.z); wb[7] = pack2(vb1.w, vb1.w);

    const u64 vsqA2 = pack2(vsA, vsA);
    const u64 vsqB2 = pack2(vsB, vsB);

    __syncthreads();

    const u64 TWO2 = pack2(2.0f, 2.0f);
    const u64 NEG1 = pack2(-1.0f, -1.0f);
    const u64 ONE1 = pack2(1.0f, 1.0f);
    const ulonglong2* rows = (const ulonglong2*)cbi;
    const u64* nq = (const u64*)csq;

    float bestA = 3.402823466e+38f, bestB = 3.402823466e+38f;
    int biA = 0, biB = 0;

    #pragma unroll 4
    for (int j = 0; j < CN / 2; ++j) {
        ulonglong2 r0 = rows[j * 4 + 0];   // d0, d1 (each u64 = {c_even, c_odd})
        ulonglong2 r1 = rows[j * 4 + 1];   // d2, d3
        ulonglong2 r2 = rows[j * 4 + 2];   // d4, d5
        ulonglong2 r3 = rows[j * 4 + 3];   // d6, d7
        u64 q = nq[j];                     // {csq_even, csq_odd}

        u64 accA = 0ULL, accB = 0ULL;      // {0.f, 0.f}
        accA = ffma2(wa[0], r0.x, accA);  accB = ffma2(wb[0], r0.x, accB);
        accA = ffma2(wa[1], r0.y, accA);  accB = ffma2(wb[1], r0.y, accB);
        accA = ffma2(wa[2], r1.x, accA);  accB = ffma2(wb[2], r1.x, accB);
        accA = ffma2(wa[3], r1.y, accA);  accB = ffma2(wb[3], r1.y, accB);
        accA = ffma2(wa[4], r2.x, accA);  accB = ffma2(wb[4], r2.x, accB);
        accA = ffma2(wa[5], r2.y, accA);  accB = ffma2(wb[5], r2.y, accB);
        accA = ffma2(wa[6], r3.x, accA);  accB = ffma2(wb[6], r3.x, accB);
        accA = ffma2(wa[7], r3.y, accA);  accB = ffma2(wb[7], r3.y, accB);

        // Reference rounding pipeline (per lane, all rn):
        //   m = 2 * vc;  d = v_sq - m;  s = d + c_sq;  argmin(s) == argmax(proba)
        // fma(m,-1,vsq) == rn(vsq-m); fma(q,1,d) == rn(q+d).
        u64 mA = fmul2(TWO2, accA);
        u64 mB = fmul2(TWO2, accB);
        u64 dA = ffma2(mA, NEG1, vsqA2);
        u64 dB = ffma2(mB, NEG1, vsqB2);
        u64 sA = ffma2(q, ONE1, dA);
        u64 sB = ffma2(q, ONE1, dB);

        float sa0, sa1, sb0, sb1;
        unpack2(sA, sa0, sa1);
        unpack2(sB, sb0, sb1);
        const int jc = j * 2;

        // argmin with strict '<' everywhere: first index wins ties, matching
        // jnp.argmax(first occurrence) on proba = -s.
        {
            float lv = (sa1 < sa0) ? sa1 : sa0;
            int   li = (sa1 < sa0) ? (jc + 1) : jc;
            if (lv < bestA) { bestA = lv; biA = li; }
        }
        {
            float lv = (sb1 < sb0) ? sb1 : sb0;
            int   li = (sb1 < sb0) ? (jc + 1) : jc;
            if (lv < bestB) { bestB = lv; biB = li; }
        }
    }

    // ---- emit winning centroid rows (copied exactly from staged codebook) ----
    {
        int base = (biA >> 1) * 16 + (biA & 1);
        float4 o0 = make_float4(cbi[base],      cbi[base + 2],
                                cbi[base + 4],  cbi[base + 6]);
        float4 o1 = make_float4(cbi[base + 8],  cbi[base + 10],
                                cbi[base + 12], cbi[base + 14]);
        float4* o = (float4*)(out + (size_t)b0 * DN + p * SDN);
        o[0] = o0; o[1] = o1;
    }
    {
        int base = (biB >> 1) * 16 + (biB & 1);
        float4 o0 = make_float4(cbi[base],      cbi[base + 2],
                                cbi[base + 4],  cbi[base + 6]);
        float4 o1 = make_float4(cbi[base + 8],  cbi[base + 10],
                                cbi[base + 12], cbi[base + 14]);
        float4* o = (float4*)(out + (size_t)b1 * DN + p * SDN);
        o[0] = o0; o[1] = o1;
    }
}

extern "C" void kernel_launch(void* const* d_in, const int* in_sizes, int n_in,
                              void* d_out, int out_size) {
    const float* vecs     = (const float*)d_in[0];
    const float* codebook = (const float*)d_in[1];
    // Defensive: inputs are (vecs: B*D = 3145728, codebook: P*C*SD = 196608)
    if (n_in >= 2 && in_sizes[0] == PN * CN * SDN && in_sizes[1] == BN * DN) {
        const float* tmp = vecs; vecs = codebook; codebook = tmp;
    }
    float* out = (float*)d_out;
    dim3 grid(BN / 256, PN);
    pq_argmax_kernel<<<grid, 128>>>(vecs, codebook, out);
}